// round 1
// baseline (speedup 1.0000x reference)
#include <cuda_runtime.h>
#include <cuda_bf16.h>
#include <math.h>

// Problem constants (fixed by the dataset)
#define NN   20000      // nodes
#define NE   320000     // edges
#define DIN  50
#define HID  1024
#define F3   726        // 6 heads * 121 classes
#define NCLS 121
#define NH3  6

// ---------------- scratch (device globals; no allocation allowed) -------------
__device__ __align__(128) float g_A[(size_t)NN * HID];   // 82 MB
__device__ __align__(128) float g_B[(size_t)NN * HID];   // 82 MB
__device__ __align__(128) float g_C[(size_t)NN * HID];   // 82 MB
__device__ int   g_deg[NN];
__device__ int   g_cursor[NN];
__device__ int   g_offs[NN + 1];
__device__ int   g_src[NE];
__device__ float g_w[NE];
__device__ float g_dis[NN];

// ---------------- degree / normalization --------------------------------------
__global__ void count_deg_kernel(const int* __restrict__ col, int* __restrict__ deg) {
    for (int e = blockIdx.x * blockDim.x + threadIdx.x; e < NE; e += gridDim.x * blockDim.x)
        atomicAdd(&deg[col[e]], 1);
}

__global__ void dis_kernel(const int* __restrict__ deg, float* __restrict__ dis) {
    int n = blockIdx.x * blockDim.x + threadIdx.x;
    if (n < NN) {
        int d = deg[n];
        dis[n] = (d > 0) ? rsqrtf((float)d) : 0.0f;
    }
}

// single-block exclusive scan of deg -> offs (N=20000, 1024 threads)
__global__ void scan_kernel(const int* __restrict__ counts, int* __restrict__ offs) {
    __shared__ int sm[1024];
    __shared__ int carry_s;
    if (threadIdx.x == 0) carry_s = 0;
    __syncthreads();
    for (int base = 0; base < NN; base += 1024) {
        int i = base + threadIdx.x;
        int v = (i < NN) ? counts[i] : 0;
        sm[threadIdx.x] = v;
        __syncthreads();
        // Hillis-Steele inclusive scan
        for (int off = 1; off < 1024; off <<= 1) {
            int t = (threadIdx.x >= off) ? sm[threadIdx.x - off] : 0;
            __syncthreads();
            sm[threadIdx.x] += t;
            __syncthreads();
        }
        int c0 = carry_s;
        if (i < NN) offs[i] = c0 + sm[threadIdx.x] - v;
        int total = sm[1023];
        __syncthreads();
        if (threadIdx.x == 0) carry_s = c0 + total;
        __syncthreads();
    }
    if (threadIdx.x == 0) offs[NN] = carry_s;
}

__global__ void fill_csr_kernel(const int* __restrict__ row, const int* __restrict__ col,
                                const int* __restrict__ offs, int* __restrict__ cursor,
                                const float* __restrict__ dis,
                                int* __restrict__ csr_src, float* __restrict__ csr_w) {
    for (int e = blockIdx.x * blockDim.x + threadIdx.x; e < NE; e += gridDim.x * blockDim.x) {
        int r = row[e], c = col[e];
        int p = atomicAdd(&cursor[c], 1);
        int slot = offs[c] + p;
        csr_src[slot] = r;
        csr_w[slot] = dis[r] * dis[c];
    }
}

// ---------------- GEMM 1: X[N,50] @ W1[50,1024] -> out[N,1024] ------------------
// 4 nodes per block; W row reused across the 4 nodes.
__global__ void gemm_small_kernel(const float* __restrict__ X, const float* __restrict__ W,
                                  float* __restrict__ out) {
    __shared__ float xr[4][DIN];
    int n0 = blockIdx.x * 4;
    int t = threadIdx.x;
    if (t < 4 * DIN) {
        int nn = t / DIN, k = t % DIN;
        xr[nn][k] = (n0 + nn < NN) ? X[(size_t)(n0 + nn) * DIN + k] : 0.0f;
    }
    __syncthreads();
    for (int j = t; j < HID; j += 256) {
        float a0 = 0.f, a1 = 0.f, a2 = 0.f, a3 = 0.f;
        #pragma unroll
        for (int k = 0; k < DIN; k++) {
            float wv = W[(size_t)k * HID + j];
            a0 = fmaf(xr[0][k], wv, a0);
            a1 = fmaf(xr[1][k], wv, a1);
            a2 = fmaf(xr[2][k], wv, a2);
            a3 = fmaf(xr[3][k], wv, a3);
        }
        if (n0 + 0 < NN) out[(size_t)(n0 + 0) * HID + j] = a0;
        if (n0 + 1 < NN) out[(size_t)(n0 + 1) * HID + j] = a1;
        if (n0 + 2 < NN) out[(size_t)(n0 + 2) * HID + j] = a2;
        if (n0 + 3 < NN) out[(size_t)(n0 + 3) * HID + j] = a3;
    }
}

// ---------------- main GEMM: 128x128x8 tiles, 8x8 per thread -------------------
// C[m*N+n] = sum_k A[m*K+k] * B[k*N+n]. K % 8 == 0 assumed (K=1024).
template <bool VECB>
__launch_bounds__(256)
__global__ void gemm128_kernel(const float* __restrict__ A, const float* __restrict__ B,
                               float* __restrict__ C, int M, int N, int K) {
    __shared__ float As[8][132];
    __shared__ float Bs[8][132];
    int tid = threadIdx.x;
    int tx = tid % 16, ty = tid / 16;
    int m0 = blockIdx.y * 128;
    int n0 = blockIdx.x * 128;

    int am = tid >> 1;           // 0..127
    int ak = (tid & 1) * 4;      // 0 or 4
    int bk = tid >> 5;           // 0..7
    int bn = (tid & 31) * 4;     // 0..124

    float acc[8][8];
    #pragma unroll
    for (int i = 0; i < 8; i++)
        #pragma unroll
        for (int j = 0; j < 8; j++) acc[i][j] = 0.f;

    for (int k0 = 0; k0 < K; k0 += 8) {
        float4 av;
        if (m0 + am < M) av = *(const float4*)(A + (size_t)(m0 + am) * K + k0 + ak);
        else             av = make_float4(0.f, 0.f, 0.f, 0.f);
        As[ak + 0][am] = av.x; As[ak + 1][am] = av.y;
        As[ak + 2][am] = av.z; As[ak + 3][am] = av.w;

        if (VECB) {
            float4 bv = *(const float4*)(B + (size_t)(k0 + bk) * N + n0 + bn);
            *(float4*)&Bs[bk][bn] = bv;
        } else {
            #pragma unroll
            for (int u = 0; u < 4; u++) {
                int n = n0 + bn + u;
                Bs[bk][bn + u] = (n < N) ? B[(size_t)(k0 + bk) * N + n] : 0.f;
            }
        }
        __syncthreads();

        #pragma unroll
        for (int k = 0; k < 8; k++) {
            float4 a0 = *(const float4*)&As[k][ty * 8];
            float4 a1 = *(const float4*)&As[k][ty * 8 + 4];
            float4 b0 = *(const float4*)&Bs[k][tx * 8];
            float4 b1 = *(const float4*)&Bs[k][tx * 8 + 4];
            float a[8] = {a0.x, a0.y, a0.z, a0.w, a1.x, a1.y, a1.z, a1.w};
            float b[8] = {b0.x, b0.y, b0.z, b0.w, b1.x, b1.y, b1.z, b1.w};
            #pragma unroll
            for (int i = 0; i < 8; i++)
                #pragma unroll
                for (int j = 0; j < 8; j++)
                    acc[i][j] = fmaf(a[i], b[j], acc[i][j]);
        }
        __syncthreads();
    }

    #pragma unroll
    for (int i = 0; i < 8; i++) {
        int m = m0 + ty * 8 + i;
        if (m < M) {
            #pragma unroll
            for (int j = 0; j < 8; j++) {
                int n = n0 + tx * 8 + j;
                if (n < N) C[(size_t)m * N + n] = acc[i][j];
            }
        }
    }
}

// ---------------- aggregation: per-node gather (no atomics) --------------------
__device__ __forceinline__ float elu_f(float x) {
    return x > 0.f ? x : (expf(x) - 1.f);
}

// F = 1024: 256 threads * float4
__global__ void agg1024_kernel(const float* __restrict__ src, const float* __restrict__ skip,
                               float* __restrict__ out,
                               const int* __restrict__ offs, const int* __restrict__ csr_src,
                               const float* __restrict__ csr_w, int do_elu) {
    int node = blockIdx.x;
    int tid = threadIdx.x;
    float4 acc = make_float4(0.f, 0.f, 0.f, 0.f);
    int beg = offs[node], end = offs[node + 1];
    for (int j = beg; j < end; j++) {
        int s = csr_src[j];
        float w = csr_w[j];
        float4 v = __ldg((const float4*)(src + (size_t)s * HID) + tid);
        acc.x = fmaf(w, v.x, acc.x);
        acc.y = fmaf(w, v.y, acc.y);
        acc.z = fmaf(w, v.z, acc.z);
        acc.w = fmaf(w, v.w, acc.w);
    }
    if (skip) {
        float4 sv = ((const float4*)(skip + (size_t)node * HID))[tid];
        acc.x += sv.x; acc.y += sv.y; acc.z += sv.z; acc.w += sv.w;
    }
    if (do_elu) {
        acc.x = elu_f(acc.x); acc.y = elu_f(acc.y);
        acc.z = elu_f(acc.z); acc.w = elu_f(acc.w);
    }
    ((float4*)(out + (size_t)node * HID))[tid] = acc;
}

// F = 726 (stride 726), skip always present, no activation
__global__ void agg726_kernel(const float* __restrict__ src, const float* __restrict__ skip,
                              float* __restrict__ out,
                              const int* __restrict__ offs, const int* __restrict__ csr_src,
                              const float* __restrict__ csr_w) {
    int node = blockIdx.x;
    int tid = threadIdx.x;
    int f0 = tid, f1 = tid + 256, f2 = tid + 512;
    bool v2 = (f2 < F3);
    float a0 = 0.f, a1 = 0.f, a2 = 0.f;
    int beg = offs[node], end = offs[node + 1];
    for (int j = beg; j < end; j++) {
        int s = csr_src[j];
        float w = csr_w[j];
        const float* r = src + (size_t)s * F3;
        a0 = fmaf(w, __ldg(r + f0), a0);
        a1 = fmaf(w, __ldg(r + f1), a1);
        if (v2) a2 = fmaf(w, __ldg(r + f2), a2);
    }
    const float* sk = skip + (size_t)node * F3;
    float* o = out + (size_t)node * F3;
    o[f0] = a0 + sk[f0];
    o[f1] = a1 + sk[f1];
    if (v2) o[f2] = a2 + sk[f2];
}

// ---------------- final mean over 6 heads ---------------------------------------
__global__ void mean_kernel(const float* __restrict__ t, float* __restrict__ out) {
    int i = blockIdx.x * blockDim.x + threadIdx.x;
    if (i < NN * NCLS) {
        int n = i / NCLS, c = i % NCLS;
        const float* r = t + (size_t)n * F3 + c;
        float s = r[0] + r[NCLS] + r[2 * NCLS] + r[3 * NCLS] + r[4 * NCLS] + r[5 * NCLS];
        out[i] = s * (1.0f / 6.0f);
    }
}

// ---------------- launcher -------------------------------------------------------
extern "C" void kernel_launch(void* const* d_in, const int* in_sizes, int n_in,
                              void* d_out, int out_size) {
    const float* X  = (const float*)d_in[0];
    const int*   ei = (const int*)d_in[1];
    const float* W1 = (const float*)d_in[2];
    const float* W2 = (const float*)d_in[3];
    const float* S2 = (const float*)d_in[4];
    const float* W3 = (const float*)d_in[5];
    const float* S3 = (const float*)d_in[6];
    float* out = (float*)d_out;

    const int* row = ei;
    const int* col = ei + NE;

    float *A, *B, *C, *dis, *w;
    int *deg, *cur, *offs, *src;
    cudaGetSymbolAddress((void**)&A,    g_A);
    cudaGetSymbolAddress((void**)&B,    g_B);
    cudaGetSymbolAddress((void**)&C,    g_C);
    cudaGetSymbolAddress((void**)&deg,  g_deg);
    cudaGetSymbolAddress((void**)&cur,  g_cursor);
    cudaGetSymbolAddress((void**)&offs, g_offs);
    cudaGetSymbolAddress((void**)&src,  g_src);
    cudaGetSymbolAddress((void**)&w,    g_w);
    cudaGetSymbolAddress((void**)&dis,  g_dis);

    // CSR build
    cudaMemsetAsync(deg, 0, NN * sizeof(int));
    cudaMemsetAsync(cur, 0, NN * sizeof(int));
    count_deg_kernel<<<512, 256>>>(col, deg);
    dis_kernel<<<(NN + 255) / 256, 256>>>(deg, dis);
    scan_kernel<<<1, 1024>>>(deg, offs);
    fill_csr_kernel<<<512, 256>>>(row, col, offs, cur, dis, src, w);

    // layer 1: A = X@W1 ; B = h1 = elu(agg(A))
    gemm_small_kernel<<<(NN + 3) / 4, 256>>>(X, W1, A);
    agg1024_kernel<<<NN, 256>>>(A, nullptr, B, offs, src, w, 1);

    // layer 2: A = h1@W2 ; C = h1@S2 ; B = h2 = elu(agg(A) + C)
    {
        dim3 grid(HID / 128, (NN + 127) / 128);
        gemm128_kernel<true><<<grid, 256>>>(B, W2, A, NN, HID, HID);
        gemm128_kernel<true><<<grid, 256>>>(B, S2, C, NN, HID, HID);
    }
    agg1024_kernel<<<NN, 256>>>(A, C, B, offs, src, w, 1);

    // layer 3: A = h2@W3 ; C = h2@S3 (width 726); B = agg(A) + C (stride 726)
    {
        dim3 grid((F3 + 127) / 128, (NN + 127) / 128);
        gemm128_kernel<false><<<grid, 256>>>(B, W3, A, NN, F3, HID);
        gemm128_kernel<false><<<grid, 256>>>(B, S3, C, NN, F3, HID);
    }
    agg726_kernel<<<NN, 256>>>(A, C, B, offs, src, w);

    // mean over 6 heads -> output [N, 121]
    mean_kernel<<<(NN * NCLS + 255) / 256, 256>>>(B, out);
}

// round 3
// speedup vs baseline: 2.3326x; 2.3326x over previous
#include <cuda_runtime.h>
#include <cuda_bf16.h>
#include <math.h>
#include <cstdint>

// Problem constants (fixed by the dataset)
#define NN   20000      // nodes
#define NE   320000     // edges
#define DIN  50
#define HID  1024
#define F3   726        // 6 heads * 121 classes
#define NCLS 121

// ---------------- scratch (device globals; no allocation allowed) -------------
__device__ __align__(128) float g_A[(size_t)NN * HID];   // 82 MB
__device__ __align__(128) float g_B[(size_t)NN * HID];   // 82 MB
__device__ __align__(128) float g_C[(size_t)NN * HID];   // 82 MB
__device__ __align__(128) __nv_bfloat16 g_Ah[(size_t)NN * HID];
__device__ __align__(128) __nv_bfloat16 g_Al[(size_t)NN * HID];
__device__ __align__(128) __nv_bfloat16 g_W2h[(size_t)HID * HID];
__device__ __align__(128) __nv_bfloat16 g_W2l[(size_t)HID * HID];
__device__ __align__(128) __nv_bfloat16 g_S2h[(size_t)HID * HID];
__device__ __align__(128) __nv_bfloat16 g_S2l[(size_t)HID * HID];
__device__ __align__(128) __nv_bfloat16 g_W3h[(size_t)F3 * HID];
__device__ __align__(128) __nv_bfloat16 g_W3l[(size_t)F3 * HID];
__device__ __align__(128) __nv_bfloat16 g_S3h[(size_t)F3 * HID];
__device__ __align__(128) __nv_bfloat16 g_S3l[(size_t)F3 * HID];
__device__ int   g_deg[NN];
__device__ int   g_cursor[NN];
__device__ int   g_offs[NN + 1];
__device__ int   g_src[NE];
__device__ float g_w[NE];
__device__ float g_dis[NN];

// ================= PTX helpers (portable: sm_80+ PTX only) =====================
__device__ __forceinline__ uint32_t smem_u32(const void* p) {
    uint32_t a;
    asm("{ .reg .u64 t; cvta.to.shared.u64 t, %1; cvt.u32.u64 %0, t; }" : "=r"(a) : "l"(p));
    return a;
}
__device__ __forceinline__ void cp16(uint32_t dst, const void* src) {
    uint64_t g = __cvta_generic_to_global(src);
    asm volatile("cp.async.cg.shared.global [%0], [%1], 16;" :: "r"(dst), "l"(g));
}
__device__ __forceinline__ void cp_commit() { asm volatile("cp.async.commit_group;" ::: "memory"); }
template <int N> __device__ __forceinline__ void cp_wait() {
    asm volatile("cp.async.wait_group %0;" :: "n"(N) : "memory");
}
__device__ __forceinline__ void ldm_x4(uint32_t* r, uint32_t addr) {
    asm volatile("ldmatrix.sync.aligned.m8n8.x4.shared.b16 {%0,%1,%2,%3}, [%4];"
                 : "=r"(r[0]), "=r"(r[1]), "=r"(r[2]), "=r"(r[3]) : "r"(addr));
}
__device__ __forceinline__ void ldm_x2(uint32_t* r, uint32_t addr) {
    asm volatile("ldmatrix.sync.aligned.m8n8.x2.shared.b16 {%0,%1}, [%2];"
                 : "=r"(r[0]), "=r"(r[1]) : "r"(addr));
}
__device__ __forceinline__ void mma16816(float* c, const uint32_t* a, const uint32_t* b) {
    asm volatile(
        "mma.sync.aligned.m16n8k16.row.col.f32.bf16.bf16.f32 "
        "{%0,%1,%2,%3}, {%4,%5,%6,%7}, {%8,%9}, {%0,%1,%2,%3};"
        : "+f"(c[0]), "+f"(c[1]), "+f"(c[2]), "+f"(c[3])
        : "r"(a[0]), "r"(a[1]), "r"(a[2]), "r"(a[3]), "r"(b[0]), "r"(b[1]));
}

// ---------------- degree / normalization --------------------------------------
__global__ void count_deg_kernel(const int* __restrict__ col, int* __restrict__ deg) {
    for (int e = blockIdx.x * blockDim.x + threadIdx.x; e < NE; e += gridDim.x * blockDim.x)
        atomicAdd(&deg[col[e]], 1);
}

__global__ void dis_kernel(const int* __restrict__ deg, float* __restrict__ dis) {
    int n = blockIdx.x * blockDim.x + threadIdx.x;
    if (n < NN) {
        int d = deg[n];
        dis[n] = (d > 0) ? rsqrtf((float)d) : 0.0f;
    }
}

__global__ void scan_kernel(const int* __restrict__ counts, int* __restrict__ offs) {
    __shared__ int sm[1024];
    __shared__ int carry_s;
    if (threadIdx.x == 0) carry_s = 0;
    __syncthreads();
    for (int base = 0; base < NN; base += 1024) {
        int i = base + threadIdx.x;
        int v = (i < NN) ? counts[i] : 0;
        sm[threadIdx.x] = v;
        __syncthreads();
        for (int off = 1; off < 1024; off <<= 1) {
            int t = (threadIdx.x >= off) ? sm[threadIdx.x - off] : 0;
            __syncthreads();
            sm[threadIdx.x] += t;
            __syncthreads();
        }
        int c0 = carry_s;
        if (i < NN) offs[i] = c0 + sm[threadIdx.x] - v;
        int total = sm[1023];
        __syncthreads();
        if (threadIdx.x == 0) carry_s = c0 + total;
        __syncthreads();
    }
    if (threadIdx.x == 0) offs[NN] = carry_s;
}

__global__ void fill_csr_kernel(const int* __restrict__ row, const int* __restrict__ col,
                                const int* __restrict__ offs, int* __restrict__ cursor,
                                const float* __restrict__ dis,
                                int* __restrict__ csr_src, float* __restrict__ csr_w) {
    for (int e = blockIdx.x * blockDim.x + threadIdx.x; e < NE; e += gridDim.x * blockDim.x) {
        int r = row[e], c = col[e];
        int p = atomicAdd(&cursor[c], 1);
        int slot = offs[c] + p;
        csr_src[slot] = r;
        csr_w[slot] = dis[r] * dis[c];
    }
}

// ---------------- layer-1 GEMM: X[N,50] @ W1[50,1024] -------------------------
__global__ void gemm1_kernel(const float* __restrict__ X, const float* __restrict__ W,
                             float* __restrict__ out) {
    __shared__ float Ws[DIN][128];
    __shared__ float Xs[16][DIN + 2];
    int t = threadIdx.x;
    int j0 = blockIdx.y * 128;
    int n0 = blockIdx.x * 16;
    for (int k = 0; k < DIN; k++) Ws[k][t] = W[(size_t)k * HID + j0 + t];
    for (int i = t; i < 16 * DIN; i += 128) {
        int nn = i / DIN, k = i % DIN;
        Xs[nn][k] = (n0 + nn < NN) ? X[(size_t)(n0 + nn) * DIN + k] : 0.0f;
    }
    __syncthreads();
    #pragma unroll 4
    for (int nn = 0; nn < 16; nn++) {
        float acc = 0.f;
        #pragma unroll
        for (int k = 0; k < DIN; k++) acc = fmaf(Xs[nn][k], Ws[k][t], acc);
        if (n0 + nn < NN) out[(size_t)(n0 + nn) * HID + j0 + t] = acc;
    }
}

// ---------------- split-precision conversion ----------------------------------
__global__ void split_kernel(const float* __restrict__ x, __nv_bfloat16* __restrict__ h,
                             __nv_bfloat16* __restrict__ l, int n) {
    int i = blockIdx.x * blockDim.x + threadIdx.x;
    if (i < n) {
        float v = x[i];
        __nv_bfloat16 hh = __float2bfloat16(v);
        float r = v - __bfloat162float(hh);
        h[i] = hh;
        l[i] = __float2bfloat16(r);
    }
}

// w[K][Nc] (row-major) -> out [Nc][K]
__global__ void splitT_kernel(const float* __restrict__ w, __nv_bfloat16* __restrict__ h,
                              __nv_bfloat16* __restrict__ l, int K, int Nc) {
    int i = blockIdx.x * blockDim.x + threadIdx.x;
    if (i < K * Nc) {
        int n = i / K, k = i % K;
        float v = w[(size_t)k * Nc + n];
        __nv_bfloat16 hh = __float2bfloat16(v);
        float r = v - __bfloat162float(hh);
        h[i] = hh;
        l[i] = __float2bfloat16(r);
    }
}

// ---------------- mma.sync GEMM ------------------------------------------------
// C[M, Nn] = A[M, 1024] * B^T, B stored [Nn][1024] (row = output col, k contiguous).
// Split precision: D += Ah*Bh + Ah*Bl + Al*Bh.
// Block 256 = 8 warps (2m x 4n), CTA tile 128x128, warp tile 64x32, K-chunk 32.
#define KC    32
#define NCH   (HID / KC)        // 32 chunks
#define RS    80                // smem row stride bytes (32 bf16 = 64B data + 16B pad)
#define ARR_B (128 * RS)        // 10240 bytes per array
#define STG_B (4 * ARR_B)       // Ah, Al, Bh, Bl
#define MMA_SMEM (2 * STG_B)    // 81920 bytes

__device__ __forceinline__ void mma_load_chunk(
    uint32_t st, int k0,
    const __nv_bfloat16* __restrict__ Ah, const __nv_bfloat16* __restrict__ Al,
    const __nv_bfloat16* __restrict__ Bh, const __nv_bfloat16* __restrict__ Bl,
    int tid, int m0, int n0, int M, int Nn) {
    const __nv_bfloat16* bases[4] = {Ah, Al, Bh, Bl};
    #pragma unroll
    for (int j = 0; j < 8; j++) {
        int arr = j >> 1;
        int row = ((j & 1) << 6) + (tid >> 2);   // 0..127
        int seg = tid & 3;                        // 16B segment
        int g0  = (arr < 2) ? m0 : n0;
        int lim = (arr < 2) ? M  : Nn;
        int grow = g0 + row;
        if (grow < lim) {
            cp16(st + arr * ARR_B + row * RS + seg * 16,
                 bases[arr] + (size_t)grow * HID + k0 + seg * 8);
        }
    }
    cp_commit();
}

__global__ void __launch_bounds__(256, 1) mma_gemm_kernel(
    const __nv_bfloat16* __restrict__ Ah, const __nv_bfloat16* __restrict__ Al,
    const __nv_bfloat16* __restrict__ Bh, const __nv_bfloat16* __restrict__ Bl,
    float* __restrict__ Cc, int M, int Nn) {
    extern __shared__ char smem[];
    uint32_t sb = smem_u32(smem);
    int tid = threadIdx.x;
    int wid = tid >> 5, lane = tid & 31;
    int wm = wid >> 2, wn = wid & 3;             // 2 x 4 warp grid
    int m0 = blockIdx.y * 128;
    int n0 = blockIdx.x * 128;

    // zero-fill rows that will never be cp'd (edge tiles), both stages
    if (m0 + 128 > M || n0 + 128 > Nn) {
        for (int e = tid; e < 1024; e += 256) {
            int s = e >> 9, rem = e & 511;
            int arr = rem >> 7, row = rem & 127;
            bool valid = (arr < 2) ? (m0 + row < M) : (n0 + row < Nn);
            if (!valid) {
                uint32_t a = sb + s * STG_B + arr * ARR_B + row * RS;
                #pragma unroll
                for (int q = 0; q < 4; q++)
                    asm volatile("st.shared.v4.b32 [%0], {%1, %1, %1, %1};"
                                 :: "r"(a + q * 16), "r"(0u) : "memory");
            }
        }
    }
    __syncthreads();

    float acc[4][4][4];
    #pragma unroll
    for (int i = 0; i < 4; i++)
        #pragma unroll
        for (int j = 0; j < 4; j++)
            #pragma unroll
            for (int q = 0; q < 4; q++) acc[i][j][q] = 0.f;

    mma_load_chunk(sb, 0, Ah, Al, Bh, Bl, tid, m0, n0, M, Nn);

    // fragment addressing (constant across chunks except stage base)
    int la = lane & 15, lha = (lane >> 4) & 1;   // A: row-in-16, k-half
    int lb = lane & 7,  lhb = (lane >> 3) & 1;   // B: row-in-8,  k-half

    for (int i = 0; i < NCH; i++) {
        int b = i & 1;
        if (i + 1 < NCH) {
            mma_load_chunk(sb + (b ^ 1) * STG_B, (i + 1) * KC, Ah, Al, Bh, Bl,
                           tid, m0, n0, M, Nn);
            cp_wait<1>();
        } else {
            cp_wait<0>();
        }
        __syncthreads();

        uint32_t st = sb + b * STG_B;
        uint32_t aB = st + (wm * 64) * RS;
        uint32_t bB = st + 2 * ARR_B + (wn * 32) * RS;

        #pragma unroll
        for (int kk = 0; kk < 2; kk++) {
            uint32_t ah[4][4], al[4][4], bh[4][2], bl[4][2];
            #pragma unroll
            for (int im = 0; im < 4; im++) {
                uint32_t ad = aB + (im * 16 + la) * RS + lha * 16 + kk * 32;
                ldm_x4(ah[im], ad);
                ldm_x4(al[im], ad + ARR_B);
            }
            #pragma unroll
            for (int in = 0; in < 4; in++) {
                uint32_t bd = bB + (in * 8 + lb) * RS + lhb * 16 + kk * 32;
                ldm_x2(bh[in], bd);
                ldm_x2(bl[in], bd + ARR_B);
            }
            #pragma unroll
            for (int im = 0; im < 4; im++)
                #pragma unroll
                for (int in = 0; in < 4; in++) {
                    mma16816(acc[im][in], ah[im], bh[in]);
                    mma16816(acc[im][in], ah[im], bl[in]);
                    mma16816(acc[im][in], al[im], bh[in]);
                }
        }
        __syncthreads();
    }

    // epilogue: fragment -> gmem (c0,c1 at row r, c2,c3 at row r+8)
    int cm = m0 + wm * 64 + (lane >> 2);
    int cn0 = n0 + wn * 32 + (lane & 3) * 2;
    #pragma unroll
    for (int im = 0; im < 4; im++) {
        int r0 = cm + im * 16;
        #pragma unroll
        for (int in = 0; in < 4; in++) {
            int c = cn0 + in * 8;
            if (c < Nn) {   // Nn even, c even -> c+1 valid too
                if (r0 < M) {
                    float2 v = make_float2(acc[im][in][0], acc[im][in][1]);
                    *(float2*)(Cc + (size_t)r0 * Nn + c) = v;
                }
                if (r0 + 8 < M) {
                    float2 v = make_float2(acc[im][in][2], acc[im][in][3]);
                    *(float2*)(Cc + (size_t)(r0 + 8) * Nn + c) = v;
                }
            }
        }
    }
}

// ---------------- aggregation: per-node gather (no atomics) --------------------
__device__ __forceinline__ float elu_f(float x) {
    return x > 0.f ? x : (expf(x) - 1.f);
}

__global__ void agg1024_kernel(const float* __restrict__ src, const float* __restrict__ skip,
                               float* __restrict__ out,
                               const int* __restrict__ offs, const int* __restrict__ csr_src,
                               const float* __restrict__ csr_w, int do_elu) {
    int node = blockIdx.x;
    int tid = threadIdx.x;
    float4 acc = make_float4(0.f, 0.f, 0.f, 0.f);
    int beg = offs[node], end = offs[node + 1];
    for (int j = beg; j < end; j++) {
        int s = csr_src[j];
        float w = csr_w[j];
        float4 v = __ldg((const float4*)(src + (size_t)s * HID) + tid);
        acc.x = fmaf(w, v.x, acc.x);
        acc.y = fmaf(w, v.y, acc.y);
        acc.z = fmaf(w, v.z, acc.z);
        acc.w = fmaf(w, v.w, acc.w);
    }
    if (skip) {
        float4 sv = ((const float4*)(skip + (size_t)node * HID))[tid];
        acc.x += sv.x; acc.y += sv.y; acc.z += sv.z; acc.w += sv.w;
    }
    if (do_elu) {
        acc.x = elu_f(acc.x); acc.y = elu_f(acc.y);
        acc.z = elu_f(acc.z); acc.w = elu_f(acc.w);
    }
    ((float4*)(out + (size_t)node * HID))[tid] = acc;
}

__global__ void agg726_kernel(const float* __restrict__ src, const float* __restrict__ skip,
                              float* __restrict__ out,
                              const int* __restrict__ offs, const int* __restrict__ csr_src,
                              const float* __restrict__ csr_w) {
    int node = blockIdx.x;
    int tid = threadIdx.x;
    int f0 = tid, f1 = tid + 256, f2 = tid + 512;
    bool v2 = (f2 < F3);
    float a0 = 0.f, a1 = 0.f, a2 = 0.f;
    int beg = offs[node], end = offs[node + 1];
    for (int j = beg; j < end; j++) {
        int s = csr_src[j];
        float w = csr_w[j];
        const float* r = src + (size_t)s * F3;
        a0 = fmaf(w, __ldg(r + f0), a0);
        a1 = fmaf(w, __ldg(r + f1), a1);
        if (v2) a2 = fmaf(w, __ldg(r + f2), a2);
    }
    const float* sk = skip + (size_t)node * F3;
    float* o = out + (size_t)node * F3;
    o[f0] = a0 + sk[f0];
    o[f1] = a1 + sk[f1];
    if (v2) o[f2] = a2 + sk[f2];
}

// ---------------- final mean over 6 heads ---------------------------------------
__global__ void mean_kernel(const float* __restrict__ t, float* __restrict__ out) {
    int i = blockIdx.x * blockDim.x + threadIdx.x;
    if (i < NN * NCLS) {
        int n = i / NCLS, c = i % NCLS;
        const float* r = t + (size_t)n * F3 + c;
        float s = r[0] + r[NCLS] + r[2 * NCLS] + r[3 * NCLS] + r[4 * NCLS] + r[5 * NCLS];
        out[i] = s * (1.0f / 6.0f);
    }
}

// ---------------- launcher -------------------------------------------------------
extern "C" void kernel_launch(void* const* d_in, const int* in_sizes, int n_in,
                              void* d_out, int out_size) {
    const float* X  = (const float*)d_in[0];
    const int*   ei = (const int*)d_in[1];
    const float* W1 = (const float*)d_in[2];
    const float* W2 = (const float*)d_in[3];
    const float* S2 = (const float*)d_in[4];
    const float* W3 = (const float*)d_in[5];
    const float* S3 = (const float*)d_in[6];
    float* out = (float*)d_out;

    const int* row = ei;
    const int* col = ei + NE;

    float *A, *B, *C, *dis, *w;
    int *deg, *cur, *offs, *src;
    __nv_bfloat16 *Ah, *Al, *W2h, *W2l, *S2h, *S2l, *W3h, *W3l, *S3h, *S3l;
    cudaGetSymbolAddress((void**)&A,    g_A);
    cudaGetSymbolAddress((void**)&B,    g_B);
    cudaGetSymbolAddress((void**)&C,    g_C);
    cudaGetSymbolAddress((void**)&deg,  g_deg);
    cudaGetSymbolAddress((void**)&cur,  g_cursor);
    cudaGetSymbolAddress((void**)&offs, g_offs);
    cudaGetSymbolAddress((void**)&src,  g_src);
    cudaGetSymbolAddress((void**)&w,    g_w);
    cudaGetSymbolAddress((void**)&dis,  g_dis);
    cudaGetSymbolAddress((void**)&Ah,   g_Ah);
    cudaGetSymbolAddress((void**)&Al,   g_Al);
    cudaGetSymbolAddress((void**)&W2h,  g_W2h);
    cudaGetSymbolAddress((void**)&W2l,  g_W2l);
    cudaGetSymbolAddress((void**)&S2h,  g_S2h);
    cudaGetSymbolAddress((void**)&S2l,  g_S2l);
    cudaGetSymbolAddress((void**)&W3h,  g_W3h);
    cudaGetSymbolAddress((void**)&W3l,  g_W3l);
    cudaGetSymbolAddress((void**)&S3h,  g_S3h);
    cudaGetSymbolAddress((void**)&S3l,  g_S3l);

    cudaFuncSetAttribute(mma_gemm_kernel, cudaFuncAttributeMaxDynamicSharedMemorySize, MMA_SMEM);

    // CSR build
    cudaMemsetAsync(deg, 0, NN * sizeof(int));
    cudaMemsetAsync(cur, 0, NN * sizeof(int));
    count_deg_kernel<<<512, 256>>>(col, deg);
    dis_kernel<<<(NN + 255) / 256, 256>>>(deg, dis);
    scan_kernel<<<1, 1024>>>(deg, offs);
    fill_csr_kernel<<<512, 256>>>(row, col, offs, cur, dis, src, w);

    // weight conversion (transpose + bf16 split)
    splitT_kernel<<<(HID * HID + 255) / 256, 256>>>(W2, W2h, W2l, HID, HID);
    splitT_kernel<<<(HID * HID + 255) / 256, 256>>>(S2, S2h, S2l, HID, HID);
    splitT_kernel<<<(HID * F3 + 255) / 256, 256>>>(W3, W3h, W3l, HID, F3);
    splitT_kernel<<<(HID * F3 + 255) / 256, 256>>>(S3, S3h, S3l, HID, F3);

    // layer 1: A = X@W1 ; B = h1 = elu(agg(A))
    {
        dim3 grid((NN + 15) / 16, HID / 128);
        gemm1_kernel<<<grid, 128>>>(X, W1, A);
    }
    agg1024_kernel<<<NN, 256>>>(A, nullptr, B, offs, src, w, 1);

    // layer 2: A = h1@W2 ; C = h1@S2 ; B = h2 = elu(agg(A) + C)
    split_kernel<<<(NN * HID + 255) / 256, 256>>>(B, Ah, Al, NN * HID);
    {
        dim3 grid(HID / 128, (NN + 127) / 128);
        mma_gemm_kernel<<<grid, 256, MMA_SMEM>>>(Ah, Al, W2h, W2l, A, NN, HID);
        mma_gemm_kernel<<<grid, 256, MMA_SMEM>>>(Ah, Al, S2h, S2l, C, NN, HID);
    }
    agg1024_kernel<<<NN, 256>>>(A, C, B, offs, src, w, 1);

    // layer 3: A = h2@W3 ; C = h2@S3 ; B = agg(A) + C (stride 726)
    split_kernel<<<(NN * HID + 255) / 256, 256>>>(B, Ah, Al, NN * HID);
    {
        dim3 grid((F3 + 127) / 128, (NN + 127) / 128);
        mma_gemm_kernel<<<grid, 256, MMA_SMEM>>>(Ah, Al, W3h, W3l, A, NN, F3);
        mma_gemm_kernel<<<grid, 256, MMA_SMEM>>>(Ah, Al, S3h, S3l, C, NN, F3);
    }
    agg726_kernel<<<NN, 256>>>(A, C, B, offs, src, w);

    // mean over 6 heads -> output [N, 121]
    mean_kernel<<<(NN * NCLS + 255) / 256, 256>>>(B, out);
}